// round 1
// baseline (speedup 1.0000x reference)
#include <cuda_runtime.h>

#define NG 2048
#define NU 16
#define NB 50
#define ND 64
#define FACTOR 0.5f

__global__ __launch_bounds__(256, 4)
void group_embedding_kernel(
    const int*   __restrict__ group_users,   // [G,U]
    const int*   __restrict__ user_lens,     // [G]
    const int*   __restrict__ beh_ids,       // [G,U,B]
    const float* __restrict__ beh_counts,    // [G,U,B]
    const int*   __restrict__ target_user,   // [G]
    const float* __restrict__ user_table,    // [N_USERS, D]
    const float* __restrict__ item_table,    // [N_ITEMS, D]
    const float* __restrict__ sim_vec,       // [N_USERS, D]
    const float* __restrict__ Wq, const float* __restrict__ bq,
    const float* __restrict__ Wk, const float* __restrict__ bk,
    const float* __restrict__ Wv, const float* __restrict__ bv,
    float*       __restrict__ out)           // [G, D]
{
    __shared__ float sSim[NU][ND];     // member similarity vectors
    __shared__ float sTsim[ND];        // target similarity vector
    __shared__ float sQ[ND];
    __shared__ float sLogit[NU];
    __shared__ float sW[NU];
    __shared__ int   sGid[NU];
    __shared__ int   sIds[NU * NB];
    __shared__ float sCoef[NU * NB];
    __shared__ float sPool[16][ND];
    __shared__ float sPooled[ND];

    const int g    = blockIdx.x;
    const int tid  = threadIdx.x;
    const int team = tid >> 4;      // 0..15
    const int lane = tid & 15;      // 0..15, owns floats [lane*4, lane*4+4)

    int L = user_lens[g];
    if (L < 1)  L = 1;
    if (L > NU) L = NU;

    // ---- Phase A0: stage 17 similarity vectors (16 members + target) ----
    for (int i = tid; i < 17 * ND; i += 256) {
        int r = i >> 6, d = i & 63;
        int idx = (r < NU) ? group_users[g * NU + r] : target_user[g];
        float v = __ldg(sim_vec + (size_t)idx * ND + d);
        if (r < NU) sSim[r][d] = v;
        else        sTsim[d]   = v;
    }
    if (tid < NU) sGid[tid] = group_users[g * NU + tid];
    __syncthreads();

    // ---- Phase A1: Q = Wq @ sim_target + bq  (64 threads) ----
    if (tid < ND) {
        float acc = __ldg(bq + tid);
        const float* wrow = Wq + tid * ND;
        #pragma unroll 8
        for (int e = 0; e < ND; e++) acc += sTsim[e] * __ldg(wrow + e);
        sQ[tid] = acc;
    }
    __syncthreads();

    // ---- Phase A2: logit[u] = FACTOR * Q . (Wk @ sim_u + bk)  (team u) ----
    {
        const int u = team;
        float part = 0.f;
        #pragma unroll
        for (int j = 0; j < 4; j++) {
            int d = lane * 4 + j;
            float acc = __ldg(bk + d);
            const float* wrow = Wk + d * ND;
            #pragma unroll 8
            for (int e = 0; e < ND; e++) acc += sSim[u][e] * __ldg(wrow + e);
            part += sQ[d] * acc;
        }
        #pragma unroll
        for (int off = 8; off; off >>= 1)
            part += __shfl_xor_sync(0xffffffffu, part, off, 16);
        if (lane == 0) sLogit[u] = FACTOR * part;
    }
    __syncthreads();

    // ---- Phase A3: masked softmax over the 16 users (warp 0) ----
    if (tid < 32) {
        int u = tid & 15;
        float v = (u < L) ? sLogit[u] : -3.402823466e38f;
        float m = v;
        #pragma unroll
        for (int off = 8; off; off >>= 1)
            m = fmaxf(m, __shfl_xor_sync(0xffffffffu, m, off, 16));
        float e = (u < L) ? __expf(v - m) : 0.f;
        float s = e;
        #pragma unroll
        for (int off = 8; off; off >>= 1)
            s += __shfl_xor_sync(0xffffffffu, s, off, 16);
        if (tid < 16) sW[u] = e / s;
    }
    __syncthreads();

    // ---- Phase B: flat (id, w*count) item list for the L valid users ----
    const int total = L * NB;
    const size_t base = (size_t)g * NU * NB;
    for (int i = tid; i < total; i += 256) {
        int u = i / NB;                       // i == u*NB + b (contiguous)
        sIds[i]  = __ldg(beh_ids + base + i);
        sCoef[i] = sW[u] * __ldg(beh_counts + base + i);
    }
    __syncthreads();

    // ---- Phase C: load-balanced weighted gather-sum ----
    float4 acc = make_float4(0.f, 0.f, 0.f, 0.f);
    if (team < L) {
        // fold in w[u] * user_table[gid[u]] as the accumulator seed
        float wgt = sW[team];
        const float4* ur = (const float4*)(user_table + (size_t)sGid[team] * ND);
        float4 v = __ldg(ur + lane);
        acc.x = wgt * v.x; acc.y = wgt * v.y; acc.z = wgt * v.z; acc.w = wgt * v.w;
    }
    #pragma unroll 4
    for (int i = team; i < total; i += 16) {
        float c = sCoef[i];
        if (c != 0.f) {
            const float4* row = (const float4*)(item_table + (size_t)sIds[i] * ND);
            float4 v = __ldg(row + lane);
            acc.x += c * v.x; acc.y += c * v.y; acc.z += c * v.z; acc.w += c * v.w;
        }
    }
    ((float4*)&sPool[team][0])[lane] = acc;
    __syncthreads();

    // ---- Phase C2: reduce the 16 team accumulators ----
    if (tid < ND) {
        float s = 0.f;
        #pragma unroll
        for (int t = 0; t < 16; t++) s += sPool[t][tid];
        sPooled[tid] = s;
    }
    __syncthreads();

    // ---- Phase D: out = Wv @ pooled + bv ----
    if (tid < ND) {
        float accv = __ldg(bv + tid);
        const float* wrow = Wv + tid * ND;
        #pragma unroll 8
        for (int e = 0; e < ND; e++) accv += sPooled[e] * __ldg(wrow + e);
        out[(size_t)g * ND + tid] = accv;
    }
}

extern "C" void kernel_launch(void* const* d_in, const int* in_sizes, int n_in,
                              void* d_out, int out_size)
{
    const int*   group_users = (const int*)  d_in[0];
    const int*   user_lens   = (const int*)  d_in[1];
    const int*   beh_ids     = (const int*)  d_in[2];
    const float* beh_counts  = (const float*)d_in[3];
    const int*   target_user = (const int*)  d_in[4];
    const float* user_table  = (const float*)d_in[5];
    const float* item_table  = (const float*)d_in[6];
    const float* sim_vec     = (const float*)d_in[7];
    const float* Wq          = (const float*)d_in[8];
    const float* bq          = (const float*)d_in[9];
    const float* Wk          = (const float*)d_in[10];
    const float* bk          = (const float*)d_in[11];
    const float* Wv          = (const float*)d_in[12];
    const float* bv          = (const float*)d_in[13];
    float*       out         = (float*)d_out;

    group_embedding_kernel<<<NG, 256>>>(
        group_users, user_lens, beh_ids, beh_counts, target_user,
        user_table, item_table, sim_vec,
        Wq, bq, Wk, bk, Wv, bv, out);
}

// round 3
// speedup vs baseline: 5.4588x; 5.4588x over previous
#include <cuda_runtime.h>

#define NG 2048
#define NU 16
#define NB 50
#define ND 64
#define FACTOR 0.5f

__global__ __launch_bounds__(256)
void group_embedding_kernel(
    const int*   __restrict__ group_users,   // [G,U]
    const int*   __restrict__ user_lens,     // [G]
    const int*   __restrict__ beh_ids,       // [G,U,B]
    const float* __restrict__ beh_counts,    // [G,U,B]
    const int*   __restrict__ target_user,   // [G]
    const float* __restrict__ user_table,    // [N_USERS, D]
    const float* __restrict__ item_table,    // [N_ITEMS, D]
    const float* __restrict__ sim_vec,       // [N_USERS, D]
    const float* __restrict__ Wq, const float* __restrict__ bq,
    const float* __restrict__ Wk, const float* __restrict__ bk,
    const float* __restrict__ Wv, const float* __restrict__ bv,
    float*       __restrict__ out)           // [G, D]
{
    __shared__ float sW[ND * 65];      // staged Wq, later reused for Wv (padded)
    __shared__ float sSim[NU][ND];     // member similarity vectors (valid users only)
    __shared__ float sTsim[ND];        // target similarity vector
    __shared__ float sQ[ND];
    __shared__ float sR[ND];           // r = Wk^T Q
    __shared__ float sLogit[NU];
    __shared__ float sWt[NU];
    __shared__ int   sGid[NU];
    __shared__ int   sIds[NU * NB];
    __shared__ float sCoef[NU * NB];
    __shared__ float sPool[16][ND];
    __shared__ float sPooled[ND];
    __shared__ float sQbkSum;          // Q . bk (scalar)

    const int g    = blockIdx.x;
    const int tid  = threadIdx.x;
    const int team = tid >> 4;      // 0..15
    const int lane = tid & 15;      // 0..15

    int L = user_lens[g];
    if (L < 1)  L = 1;
    if (L > NU) L = NU;

    // ---- Stage Wq into shared, coalesced ----
    #pragma unroll
    for (int i = tid; i < ND * ND; i += 256) {
        int r = i >> 6, c = i & 63;
        sW[r * 65 + c] = __ldg(Wq + i);
    }

    // ---- Stage L member sim vectors + target sim vector ----
    for (int i = tid; i < (L + 1) * ND; i += 256) {
        int r = i >> 6, d = i & 63;
        int idx = (r < L) ? group_users[g * NU + r] : target_user[g];
        float v = __ldg(sim_vec + (size_t)idx * ND + d);
        if (r < L) sSim[r][d] = v;
        else       sTsim[d]   = v;
    }
    if (tid < NU) sGid[tid] = group_users[g * NU + tid];
    __syncthreads();

    // ---- Q = Wq @ Tsim + bq (shared, conflict-free via pad 65) ----
    if (tid < ND) {
        float acc = __ldg(bq + tid);
        const float* wrow = sW + tid * 65;
        #pragma unroll 16
        for (int e = 0; e < ND; e++) acc += wrow[e] * sTsim[e];
        sQ[tid] = acc;
    }
    __syncthreads();

    // ---- r = Wk^T Q (coalesced column access); warp 0 also computes Q.bk ----
    if (tid < ND) {
        float rr = 0.f;
        #pragma unroll 16
        for (int d = 0; d < ND; d++) rr += sQ[d] * __ldg(Wk + d * ND + tid);
        sR[tid] = rr;
    }
    if (tid < 32) {
        float p = sQ[tid] * __ldg(bk + tid) + sQ[tid + 32] * __ldg(bk + tid + 32);
        #pragma unroll
        for (int off = 16; off; off >>= 1)
            p += __shfl_xor_sync(0xffffffffu, p, off);
        if (tid == 0) sQbkSum = p;
    }
    __syncthreads();

    // ---- logit[u] = FACTOR * (r . sim_u + Q.bk) — ALL teams (no divergent shfl) ----
    {
        int uu = (team < L) ? team : 0;   // clamp: invalid teams compute a discarded value
        float part = 0.f;
        #pragma unroll
        for (int j = 0; j < 4; j++) {
            int e = lane * 4 + j;
            part += sR[e] * sSim[uu][e];
        }
        #pragma unroll
        for (int off = 8; off; off >>= 1)
            part += __shfl_xor_sync(0xffffffffu, part, off, 16);
        if (lane == 0) sLogit[team] = FACTOR * (part + sQbkSum);
    }
    __syncthreads();

    // ---- masked softmax over the L users (warp 0, full warp active) ----
    if (tid < 32) {
        int u = tid & 15;
        float v = (u < L) ? sLogit[u] : -3.402823466e38f;
        float m = v;
        #pragma unroll
        for (int off = 8; off; off >>= 1)
            m = fmaxf(m, __shfl_xor_sync(0xffffffffu, m, off, 16));
        float e = (u < L) ? __expf(v - m) : 0.f;
        float s = e;
        #pragma unroll
        for (int off = 8; off; off >>= 1)
            s += __shfl_xor_sync(0xffffffffu, s, off, 16);
        if (tid < 16) sWt[u] = e / s;
    }
    __syncthreads();

    // ---- flat (id, w*count) item list for the L valid users ----
    const int total = L * NB;
    const size_t base = (size_t)g * NU * NB;
    for (int i = tid; i < total; i += 256) {
        int u = i / NB;
        sIds[i]  = __ldg(beh_ids + base + i);
        sCoef[i] = sWt[u] * __ldg(beh_counts + base + i);
    }

    // ---- Pre-stage Wv into sW (sW free: Q already computed) ----
    #pragma unroll
    for (int i = tid; i < ND * ND; i += 256) {
        int r = i >> 6, c = i & 63;
        sW[r * 65 + c] = __ldg(Wv + i);
    }
    __syncthreads();

    // ---- load-balanced weighted gather-sum (team-strided) ----
    float4 acc = make_float4(0.f, 0.f, 0.f, 0.f);
    if (team < L) {
        float wgt = sWt[team];
        const float4* ur = (const float4*)(user_table + (size_t)sGid[team] * ND);
        float4 v = __ldg(ur + lane);
        acc.x = wgt * v.x; acc.y = wgt * v.y; acc.z = wgt * v.z; acc.w = wgt * v.w;
    }
    #pragma unroll 4
    for (int i = team; i < total; i += 16) {
        float c = sCoef[i];
        if (c != 0.f) {
            const float4* row = (const float4*)(item_table + (size_t)sIds[i] * ND);
            float4 v = __ldg(row + lane);
            acc.x += c * v.x; acc.y += c * v.y; acc.z += c * v.z; acc.w += c * v.w;
        }
    }
    ((float4*)&sPool[team][0])[lane] = acc;
    __syncthreads();

    // ---- reduce the 16 team accumulators ----
    if (tid < ND) {
        float s = 0.f;
        #pragma unroll
        for (int t = 0; t < 16; t++) s += sPool[t][tid];
        sPooled[tid] = s;
    }
    __syncthreads();

    // ---- out = Wv @ pooled + bv (from shared, conflict-free) ----
    if (tid < ND) {
        float accv = __ldg(bv + tid);
        const float* wrow = sW + tid * 65;
        #pragma unroll 16
        for (int e = 0; e < ND; e++) accv += wrow[e] * sPooled[e];
        out[(size_t)g * ND + tid] = accv;
    }
}

extern "C" void kernel_launch(void* const* d_in, const int* in_sizes, int n_in,
                              void* d_out, int out_size)
{
    const int*   group_users = (const int*)  d_in[0];
    const int*   user_lens   = (const int*)  d_in[1];
    const int*   beh_ids     = (const int*)  d_in[2];
    const float* beh_counts  = (const float*)d_in[3];
    const int*   target_user = (const int*)  d_in[4];
    const float* user_table  = (const float*)d_in[5];
    const float* item_table  = (const float*)d_in[6];
    const float* sim_vec     = (const float*)d_in[7];
    const float* Wq          = (const float*)d_in[8];
    const float* bq          = (const float*)d_in[9];
    const float* Wk          = (const float*)d_in[10];
    const float* bk          = (const float*)d_in[11];
    const float* Wv          = (const float*)d_in[12];
    const float* bv          = (const float*)d_in[13];
    float*       out         = (float*)d_out;

    group_embedding_kernel<<<NG, 256>>>(
        group_users, user_lens, beh_ids, beh_counts, target_user,
        user_table, item_table, sim_vec,
        Wq, bq, Wk, bk, Wv, bv, out);
}